// round 14
// baseline (speedup 1.0000x reference)
#include <cuda_runtime.h>
#include <cuda_fp16.h>
#include <math.h>

#define NN 80000
#define DD 64
#define EE 1280000
#define CAP 128   // padded adjacency capacity per node

// Scratch (__device__ globals; no allocation allowed in kernel_launch)
__device__ uint2 g_hH[NN * 16];    // h' = (X@W)*dinv packed fp16 (16 uint2/row)
__device__ uint2 g_H2[NN * 16];    // H = relu(...) packed fp16
__device__ float g_gg[NN];
__device__ int   g_cnt[NN];        // out-degree (gate denominator)
__device__ int   g_deg[NN];        // in-degree == build cursor
__device__ int   g_adj[NN * CAP];  // padded adjacency: srcs bucketed by dst

// ---------------------------------------------------------------------------
__global__ void k_init(int n) {
    int i = blockIdx.x * blockDim.x + threadIdx.x;
    if (i < n) {
        g_deg[i] = 0;
        g_cnt[i] = 0;
        g_gg[i]  = 0.f;
    }
}

// ---------------------------------------------------------------------------
// k_build: ONE indexing pass. Slot-claim atomic IS the degree counter.
// ---------------------------------------------------------------------------
__global__ void k_build(const int* __restrict__ src, const int* __restrict__ dst, int e) {
    int i = blockIdx.x * blockDim.x + threadIdx.x;
    if (i < e) {
        int s = src[i], d = dst[i];
        int pos = atomicAdd(&g_deg[d], 1);
        if (pos < CAP) g_adj[d * CAP + pos] = s;
        atomicAdd(&g_cnt[s], 1);
    }
}

// ---------------------------------------------------------------------------
// k_gemm: h' = (X @ W) * dinv_row, 4x4 register tile. dinv folded into the
// pack epilogue (runs after k_build, so g_deg is final). fp16 packed output.
// ---------------------------------------------------------------------------
#define XS_STRIDE 68
__global__ void __launch_bounds__(256) k_gemm(const float* __restrict__ X,
                                              const float* __restrict__ W, int n) {
    __shared__ float  Xsh[64 * XS_STRIDE];   // Xsh[k][row]
    __shared__ float4 Wsh[64 * 16];          // Wsh[k][cg]

    int tid  = threadIdx.x;
    int base = blockIdx.x * 64;

    const float4* W4 = (const float4*)W;
#pragma unroll
    for (int i = 0; i < 4; i++) Wsh[tid + 256 * i] = W4[tid + 256 * i];

#pragma unroll
    for (int i = 0; i < 4; i++) {
        int idx = tid + 256 * i;
        int row = idx & 63;
        int kk  = idx >> 6;
        int gr  = base + row;
        float4 v = (gr < n) ? ((const float4*)(X + (size_t)gr * 64))[kk]
                            : make_float4(0.f, 0.f, 0.f, 0.f);
        int k0 = kk * 4;
        Xsh[(k0 + 0) * XS_STRIDE + row] = v.x;
        Xsh[(k0 + 1) * XS_STRIDE + row] = v.y;
        Xsh[(k0 + 2) * XS_STRIDE + row] = v.z;
        Xsh[(k0 + 3) * XS_STRIDE + row] = v.w;
    }
    __syncthreads();

    int cg = tid & 15;
    int rg = tid >> 4;

    float4 acc0 = make_float4(0.f, 0.f, 0.f, 0.f);
    float4 acc1 = make_float4(0.f, 0.f, 0.f, 0.f);
    float4 acc2 = make_float4(0.f, 0.f, 0.f, 0.f);
    float4 acc3 = make_float4(0.f, 0.f, 0.f, 0.f);

#pragma unroll
    for (int k = 0; k < 64; k++) {
        float4 w  = Wsh[k * 16 + cg];
        float4 xv = *(const float4*)&Xsh[k * XS_STRIDE + rg * 4];
        acc0.x += xv.x * w.x; acc0.y += xv.x * w.y; acc0.z += xv.x * w.z; acc0.w += xv.x * w.w;
        acc1.x += xv.y * w.x; acc1.y += xv.y * w.y; acc1.z += xv.y * w.z; acc1.w += xv.y * w.w;
        acc2.x += xv.z * w.x; acc2.y += xv.z * w.y; acc2.z += xv.z * w.z; acc2.w += xv.z * w.w;
        acc3.x += xv.w * w.x; acc3.y += xv.w * w.y; acc3.z += xv.w * w.z; acc3.w += xv.w * w.w;
    }

    int r0 = base + rg * 4;
#pragma unroll
    for (int j = 0; j < 4; j++) {
        float4 a = (j == 0) ? acc0 : (j == 1) ? acc1 : (j == 2) ? acc2 : acc3;
        int row = r0 + j;
        if (row < n) {
            float di = rsqrtf((float)(g_deg[row] + 1));   // fold dinv into h'
            __half2 lo = __floats2half2_rn(a.x * di, a.y * di);
            __half2 hi = __floats2half2_rn(a.z * di, a.w * di);
            uint2 p;
            p.x = *(unsigned int*)&lo;
            p.y = *(unsigned int*)&hi;
            g_hH[row * 16 + cg] = p;
        }
    }
}

// ---------------------------------------------------------------------------
// k_agg: warp per node, PAIRED neighbors. Lanes 0-15 take even neighbors,
// 16-31 odd; each lane loads uint2 (4 halves), so one LDG.64 covers TWO
// neighbor rows. Neighbor ids fetched as int4 (4 ids / LDG.128, uniform).
// Halves combined with one shfl-xor(16) at the end. agg = dinv_d*(sum+self).
// ---------------------------------------------------------------------------
__global__ void __launch_bounds__(256) k_agg(const float* __restrict__ b, int n) {
    int warp = (blockIdx.x * blockDim.x + threadIdx.x) >> 5;
    int lane = threadIdx.x & 31;
    if (warp >= n) return;
    int d = warp;
    int sel = lane >> 4;     // which neighbor of the pair
    int sub = lane & 15;     // column group: cols 4*sub .. 4*sub+3

    const uint2* h2 = (const uint2*)g_hH;  // 16 uint2 per node row
    int cnt = g_deg[d];
    float dinv_d = rsqrtf((float)(cnt + 1));   // +1 self loop
    const int* row = &g_adj[d * CAP];

    float4 acc = make_float4(0.f, 0.f, 0.f, 0.f);

    int j = 0;
    for (; j + 4 <= cnt; j += 4) {           // 4 neighbors per iter (2 pairs)
        int4 i4 = *(const int4*)&row[j];     // uniform LDG.128
        int sA = sel ? i4.y : i4.x;
        int sB = sel ? i4.w : i4.z;
        uint2 va = h2[sA * 16 + sub];
        uint2 vb = h2[sB * 16 + sub];
        float2 a0 = __half22float2(*(const __half2*)&va.x);
        float2 a1 = __half22float2(*(const __half2*)&va.y);
        float2 b0 = __half22float2(*(const __half2*)&vb.x);
        float2 b1 = __half22float2(*(const __half2*)&vb.y);
        acc.x += a0.x + b0.x;
        acc.y += a0.y + b0.y;
        acc.z += a1.x + b1.x;
        acc.w += a1.y + b1.y;
    }
    for (; j + 2 <= cnt; j += 2) {           // one pair
        int2 i2 = *(const int2*)&row[j];
        int s = sel ? i2.y : i2.x;
        uint2 v = h2[s * 16 + sub];
        float2 a0 = __half22float2(*(const __half2*)&v.x);
        float2 a1 = __half22float2(*(const __half2*)&v.y);
        acc.x += a0.x; acc.y += a0.y; acc.z += a1.x; acc.w += a1.y;
    }
    if (j < cnt && sel == 0) {               // odd tail: lanes 0-15 only
        int s = row[j];
        uint2 v = h2[s * 16 + sub];
        float2 a0 = __half22float2(*(const __half2*)&v.x);
        float2 a1 = __half22float2(*(const __half2*)&v.y);
        acc.x += a0.x; acc.y += a0.y; acc.z += a1.x; acc.w += a1.y;
    }

    // combine even/odd halves (lane l <-> l^16 hold same columns)
    acc.x += __shfl_xor_sync(0xffffffffu, acc.x, 16);
    acc.y += __shfl_xor_sync(0xffffffffu, acc.y, 16);
    acc.z += __shfl_xor_sync(0xffffffffu, acc.z, 16);
    acc.w += __shfl_xor_sync(0xffffffffu, acc.w, 16);

    if (sel == 0) {                          // epilogue: lanes 0-15, 8B each
        uint2 hv = h2[d * 16 + sub];         // self loop h'[d]
        float2 h0 = __half22float2(*(const __half2*)&hv.x);
        float2 h1 = __half22float2(*(const __half2*)&hv.y);
        float4 bb = ((const float4*)b)[sub];
        float r0 = fmaxf(fmaf(acc.x + h0.x, dinv_d, bb.x), 0.f);
        float r1 = fmaxf(fmaf(acc.y + h0.y, dinv_d, bb.y), 0.f);
        float r2 = fmaxf(fmaf(acc.z + h1.x, dinv_d, bb.z), 0.f);
        float r3 = fmaxf(fmaf(acc.w + h1.y, dinv_d, bb.w), 0.f);
        __half2 lo = __floats2half2_rn(r0, r1);
        __half2 hi = __floats2half2_rn(r2, r3);
        uint2 p;
        p.x = *(unsigned int*)&lo;
        p.y = *(unsigned int*)&hi;
        ((uint2*)g_H2)[d * 16 + sub] = p;
    }
}

// ---------------------------------------------------------------------------
// k_gate: edge-parallel. gg[src] += ||H_s - H_d||^2. 8 lanes/edge, uint4 per
// lane. Diff taken in fp16 (HSUB2) BEFORE conversion: 1 HSUB2 + 1 cvt + 2 FMA
// per half2 instead of 2 cvt + 2 sub + 2 FMA.
// ---------------------------------------------------------------------------
__global__ void k_gate(const int* __restrict__ src, const int* __restrict__ dst, int e) {
    int t = blockIdx.x * blockDim.x + threadIdx.x;
    int ei = t >> 3;
    int lane = t & 7;
    if (ei >= e) return;
    int r = src[ei];
    int c = dst[ei];
    const uint4* H = (const uint4*)g_H2;
    uint4 a = __ldg(&H[r * 8 + lane]);
    uint4 b = __ldg(&H[c * 8 + lane]);
    const unsigned int* au = (const unsigned int*)&a;
    const unsigned int* bu = (const unsigned int*)&b;
    float s = 0.f;
#pragma unroll
    for (int j = 0; j < 4; j++) {
        __half2 dh = __hsub2(*(const __half2*)&au[j], *(const __half2*)&bu[j]);
        float2 df = __half22float2(dh);
        s = fmaf(df.x, df.x, s);
        s = fmaf(df.y, df.y, s);
    }
    s += __shfl_xor_sync(0xffffffffu, s, 4);
    s += __shfl_xor_sync(0xffffffffu, s, 2);
    s += __shfl_xor_sync(0xffffffffu, s, 1);
    if (lane == 0) atomicAdd(&g_gg[r], s);
}

__global__ void k_out(float* __restrict__ out, int n) {
    int i = blockIdx.x * blockDim.x + threadIdx.x;
    if (i < n) out[i] = tanhf(g_gg[i] / fmaxf((float)g_cnt[i], 1.f));
}

// ---------------------------------------------------------------------------
extern "C" void kernel_launch(void* const* d_in, const int* in_sizes, int n_in,
                              void* d_out, int out_size) {
    const float* X  = (const float*)d_in[0];
    const int*   ei = (const int*)d_in[1];
    const float* W  = (const float*)d_in[2];
    const float* b  = (const float*)d_in[3];
    float* out = (float*)d_out;

    int n = in_sizes[0] / DD;   // 80000
    int e = in_sizes[1] / 2;    // 1280000
    const int* src = ei;
    const int* dst = ei + e;

    const int T = 256;
    int g_n    = (n + T - 1) / T;
    int g_e    = (e + T - 1) / T;
    int g_rows = (n + 63) / 64;
    int g_warp = (n * 32 + T - 1) / T;
    long long e8 = (long long)e * 8;
    int g_e8 = (int)((e8 + T - 1) / T);

    k_init <<<g_n, T>>>(n);
    k_build<<<g_e, T>>>(src, dst, e);
    k_gemm <<<g_rows, T>>>(X, W, n);
    k_agg  <<<g_warp, T>>>(b, n);
    k_gate <<<g_e8, T>>>(src, dst, e);
    k_out  <<<g_n, T>>>(out, n);
}